// round 17
// baseline (speedup 1.0000x reference)
#include <cuda_runtime.h>
#include <math_constants.h>

// NDE loss, v7 — R16's measured-best streaming phase (row-quarter tiles,
// prefetched ticket) fused with an in-kernel epilogue:
//   * grid = #SMs*8 CTAs pull tiles (row r, quarter q; ~12.5K floats) off a
//     global atomic ticket; next ticket prefetched at tile top, published at
//     tile end (atomic latency hidden under ~14K cycles of work).
//   * per tile: partial streaming logsumexp (float4 x4 per iter, __ldcs),
//     block reduce, write to g_part[r*4+q] (position-keyed => deterministic).
//   * gen-row segment 0: warp 0 additionally does that row's entity gathers
//     (lanes 0..2E-1 concurrent, fixed-order shfl sum) into g_gather[rr].
//   * last CTA (fence + done counter): merges each row's 4 partials in fixed
//     order, lse = m + logf(s), row contribution, fixed-order double reduce,
//     writes scalar, resets counters (graph-replay safe).
//
// out = (1/(N*E*T)) * sum_{n,t,e} ( gen[n,t,ent] - ori[rep[n],t,ent] )
//     + (1/(N*T))   * sum_{n,t}   ( lse_ori[rep[n],t] - lse_gen[n,t] )
//
// Bench shapes: B0=8, N=16, T=128, V=50257, E=4.

#define T_DIM 128
#define V_DIM 50257
#define NTHREADS 256
#define QUARTERS 4
#define MAX_ROWS ((64 + 128) * T_DIM)
#define MAX_GEN_ROWS (128 * T_DIM)

__device__ float        g_part_m[MAX_ROWS * QUARTERS];
__device__ float        g_part_s[MAX_ROWS * QUARTERS];
__device__ double       g_gather[MAX_GEN_ROWS];
__device__ unsigned int g_ticket;      // zero-init; reset by last CTA
__device__ unsigned int g_done_count;  // zero-init; reset by last CTA

__device__ __forceinline__ void lse_merge(float& m, float& s, float om, float os) {
    float nm = fmaxf(m, om);
    s = s * __expf(fmaxf(m - nm, -87.0f)) + os * __expf(fmaxf(om - nm, -87.0f));
    m = nm;
}
__device__ __forceinline__ float max4(float4 a) {
    return fmaxf(fmaxf(a.x, a.y), fmaxf(a.z, a.w));
}
__device__ __forceinline__ float expsum4(float4 a, float nm) {
    return __expf(a.x - nm) + __expf(a.y - nm) + __expf(a.z - nm) + __expf(a.w - nm);
}

// repeat_interleave(arange(B0), lens, total_repeat_length=N):
// truncate at N; pad with last element (B0-1) if sum < N.
__device__ __forceinline__ int rep_of(const int* lens, int B0, int N, int n) {
    int pre = 0;
    for (int b = 0; b < B0; b++) {
        int L = lens[b];
        if (n < pre + L) return b;
        pre += L;
    }
    return B0 - 1;
}

__global__ void __launch_bounds__(NTHREADS, 8)
nde_kernel(const float* __restrict__ ori, const float* __restrict__ gen,
           const int* __restrict__ lens, const int* __restrict__ ents,
           int B0, int N, int E, float* __restrict__ out) {
    const int tid = threadIdx.x;
    const int lane = tid & 31;
    const int B = NTHREADS;
    const int oriRows = B0 * T_DIM;
    const int totalRows = (B0 + N) * T_DIM;
    const int totalTiles = totalRows * QUARTERS;
    const unsigned full = 0xffffffffu;

    __shared__ int sh_cur;
    __shared__ float shm[NTHREADS / 32];
    __shared__ float shs[NTHREADS / 32];
    __shared__ bool sh_last;

    if (tid == 0) sh_cur = (int)atomicAdd(&g_ticket, 1u);
    __syncthreads();

    // ------------------ streaming phase (identical to R16 best) -----------
    for (;;) {
        const int tile = sh_cur;
        if (tile >= totalTiles) break;

        int nxt = 0x7fffffff;
        if (tid == 0) nxt = (int)atomicAdd(&g_ticket, 1u);  // prefetch

        const int r = tile >> 2;
        const int q = tile & 3;
        const int a = (V_DIM * q) >> 2;
        const int b = (V_DIM * (q + 1)) >> 2;
        const int len = b - a;

        const bool isGen = r >= oriRows;
        const float* rowbase = isGen
            ? gen + (size_t)(r - oriRows) * V_DIM
            : ori + (size_t)r * V_DIM;
        const float* p = rowbase + a;

        float m = -CUDART_INF_F;
        float s = 0.0f;

        // scalar peel to 16B alignment
        const int mis = (int)(((size_t)p >> 2) & 3u);
        const int pre = mis ? ((4 - mis) < len ? (4 - mis) : len) : 0;
        if (tid < pre) { m = p[tid]; s = 1.0f; }

        const int n4 = (len - pre) >> 2;
        const float4* __restrict__ p4 = reinterpret_cast<const float4*>(p + pre);

        int j = tid;
        for (; j + 3 * B < n4; j += 4 * B) {
            float4 x0 = __ldcs(&p4[j]);
            float4 x1 = __ldcs(&p4[j + B]);
            float4 x2 = __ldcs(&p4[j + 2 * B]);
            float4 x3 = __ldcs(&p4[j + 3 * B]);
            float lm = fmaxf(fmaxf(max4(x0), max4(x1)), fmaxf(max4(x2), max4(x3)));
            float nm = fmaxf(m, lm);
            s = s * __expf(m - nm)
                + expsum4(x0, nm) + expsum4(x1, nm)
                + expsum4(x2, nm) + expsum4(x3, nm);
            m = nm;
        }
        for (; j < n4; j += B) {
            float4 x0 = __ldcs(&p4[j]);
            float nm = fmaxf(m, max4(x0));
            s = s * __expf(m - nm) + expsum4(x0, nm);
            m = nm;
        }
        {
            const int done = pre + 4 * n4;
            const int rem = len - done;
            if (tid < rem) {
                float x = p[done + tid];
                float nm = fmaxf(m, x);
                s = s * __expf(m - nm) + __expf(x - nm);
                m = nm;
            }
        }

        // block reduce (m, s)
        #pragma unroll
        for (int off = 16; off; off >>= 1) {
            float om = __shfl_xor_sync(full, m, off);
            float os = __shfl_xor_sync(full, s, off);
            lse_merge(m, s, om, os);
        }
        if (lane == 0) { shm[tid >> 5] = m; shs[tid >> 5] = s; }
        __syncthreads();
        if (tid == 0) {
            float M = shm[0], S = shs[0];
            #pragma unroll
            for (int w = 1; w < NTHREADS / 32; w++) lse_merge(M, S, shm[w], shs[w]);
            g_part_m[tile] = M;
            g_part_s[tile] = S;
            sh_cur = nxt;  // publish prefetched ticket
        }

        // entity gathers: attached to gen-row segment 0; warp 0 only.
        if (isGen && q == 0 && tid < 32) {
            const int rr = r - oriRows;
            const int n = rr / T_DIM;
            const int t = rr - n * T_DIM;
            double gval = 0.0;
            if (lane < 2 * E) {
                const int e = (lane < E) ? lane : lane - E;
                const int col = ents[n * E + e];
                if (lane < E) {
                    gval = (double)gen[((size_t)n * T_DIM + t) * V_DIM + col];
                } else {
                    const int rep = rep_of(lens, B0, N, n);
                    gval = -(double)ori[((size_t)rep * T_DIM + t) * V_DIM + col];
                }
            }
            #pragma unroll
            for (int off = 16; off; off >>= 1)
                gval += __shfl_xor_sync(full, gval, off);
            if (lane == 0) g_gather[rr] = gval;
        }
        __syncthreads();
    }

    // ------------------ last-CTA epilogue ---------------------------------
    if (tid == 0) {
        __threadfence();
        unsigned prev = atomicAdd(&g_done_count, 1u);
        sh_last = (prev == gridDim.x - 1);
    }
    __syncthreads();
    if (!sh_last) return;
    __threadfence();  // acquire all g_part / g_gather writes

    const double invNT = 1.0 / ((double)N * (double)T_DIM);
    double acc = 0.0;
    for (int r = tid; r < totalRows; r += NTHREADS) {
        float m = g_part_m[r * QUARTERS];
        float s = g_part_s[r * QUARTERS];
        #pragma unroll
        for (int q = 1; q < QUARTERS; q++)
            lse_merge(m, s, g_part_m[r * QUARTERS + q], g_part_s[r * QUARTERS + q]);
        const double lse = (double)m + (double)logf(s);

        if (r < oriRows) {
            // weight w_b = # of n with rep[n]==b (jnp pad-with-last)
            const int b = r / T_DIM;
            int pre = 0, w = 0;
            for (int k = 0; k < B0; k++) {
                int L = lens[k];
                if (k == b) {
                    int lo = pre < N ? pre : N;
                    int hi = (pre + L) < N ? (pre + L) : N;
                    w = hi - lo;
                }
                pre += L;
            }
            if (b == B0 - 1 && pre < N) w += N - pre;
            acc += lse * (double)w * invNT;
        } else {
            acc += g_gather[r - oriRows] * invNT / (double)E - lse * invNT;
        }
    }

    __shared__ double red[NTHREADS];
    red[tid] = acc;
    __syncthreads();
    #pragma unroll
    for (int off = NTHREADS / 2; off; off >>= 1) {
        if (tid < off) red[tid] += red[tid + off];
        __syncthreads();
    }
    if (tid == 0) {
        out[0] = (float)red[0];
        g_done_count = 0;  // reset for graph replay
        g_ticket = 0;
    }
}

extern "C" void kernel_launch(void* const* d_in, const int* in_sizes, int n_in,
                              void* d_out, int out_size) {
    const float* ori  = (const float*)d_in[0];  // [B0, T, V]
    const float* gen  = (const float*)d_in[1];  // [N,  T, V]
    const int*   lens = (const int*)d_in[2];    // [B0]
    const int*   ents = (const int*)d_in[3];    // [N, E]

    const int B0 = in_sizes[0] / (T_DIM * V_DIM);
    const int N  = in_sizes[1] / (T_DIM * V_DIM);
    const int E  = in_sizes[3] / N;

    int sms = 148;
    cudaDeviceGetAttribute(&sms, cudaDevAttrMultiProcessorCount, 0);
    const int nBlocks = sms * 8;

    nde_kernel<<<nBlocks, NTHREADS>>>(ori, gen, lens, ents, B0, N, E,
                                      (float*)d_out);
}